// round 9
// baseline (speedup 1.0000x reference)
#include <cuda_runtime.h>

// YOLOV3TargetMerger: b=32, N=22743, M=50, C=80
// Inputs: 0 box_preds[b,N,4] 1 gt_boxes[b,M,4] 2 obj_t[b,N,1]
//         3 centers_t[b,N,2] 4 scales_t[b,N,2] 5 weights_t[b,N,2] 6 clas_t[b,N,80]
// Output (concat f32): obj[S], cen[2S], sca[2S], wei[2S], cls_t[80S], cls_m[80S]

#define BATCH 32
#define MGT   50
#define NCLS  80
#define C4    (NCLS / 4)
#define THR   0.7f
#define EPSF  1e-12f
#define CLS_BLOCKS 2368      // 148 SMs * 16 CTAs
#define CLS_THREADS 256
#define UNROLL 4

__global__ void __launch_bounds__(256) merge_main_kernel(
    const float4* __restrict__ bp,
    const float4* __restrict__ gt,
    const float*  __restrict__ obj,
    const float2* __restrict__ cen,
    const float2* __restrict__ sca,
    const float2* __restrict__ wei,
    float* __restrict__ out,
    int N, long long S)
{
    __shared__ float4 sgt[MGT];
    __shared__ float  sarea[MGT];
    __shared__ int    scnt;

    const int b = blockIdx.y;
    const int t = threadIdx.x;

    // compact gt boxes: non-positive width/height => inter==0 vs every anchor,
    // which can never produce a hit (needs d>0, then 0 > 0.7*d is false).
    if (t == 0) scnt = 0;
    __syncthreads();
    if (t < MGT) {
        const float4 g = gt[b * MGT + t];
        if (g.z > g.x && g.w > g.y) {
            const int k = atomicAdd(&scnt, 1);
            sgt[k]   = g;
            sarea[k] = (g.z - g.x) * (g.w - g.y);
        }
    }
    __syncthreads();
    const int K = scnt;                       // ~12.5 expected

    const int n = blockIdx.x * blockDim.x + t;
    if (n >= N) return;
    const long long i = (long long)b * N + n;

    const float o    = obj[i];
    const bool  mask = (o > 0.0f);

    float objout;
    if (mask) {
        objout = o;                           // IOU result unused -> skip loop
    } else {
        const float4 p = bp[i];
        const float area_p = (p.z - p.x) * (p.w - p.y);

        bool hit = false, ambig = false;
        for (int m = 0; m < K; m++) {
            const float4 g = sgt[m];
            const float w = fmaxf(fminf(p.z, g.z) - fmaxf(p.x, g.x), 0.0f);
            const float h = fmaxf(fminf(p.w, g.w) - fmaxf(p.y, g.y), 0.0f);
            const float inter = w * h;
            float u = area_p + sarea[m];
            u = u - inter;
            const float d = u + EPSF;         // ref denominator, same op order
            const float thr  = THR * d;
            const float diff = inter - thr;
            const float marg = 1e-6f * thr;
            const bool pos = (d > 0.0f);
            hit   = hit   | (pos & (diff >  marg));
            ambig = ambig | (pos & (fabsf(diff) <= marg));
        }
        if (ambig) {                          // rare: redo exactly (IEEE div)
            hit = false;
            for (int m = 0; m < K; m++) {
                const float4 g = sgt[m];
                const float w = fmaxf(fminf(p.z, g.z) - fmaxf(p.x, g.x), 0.0f);
                const float h = fmaxf(fminf(p.w, g.w) - fmaxf(p.y, g.y), 0.0f);
                const float inter = w * h;
                float u = area_p + sarea[m];
                u = u - inter;
                const float d = u + EPSF;
                hit = hit | ((inter / d) > THR);  // d<0 -> iou<=0 -> false (== ref)
            }
        }
        objout = hit ? -1.0f : 0.0f;
    }

    out[i] = objout;

    float2 c, s, w;
    if (mask) {
        c = cen[i]; s = sca[i]; w = wei[i];   // only read when used
    } else {
        c = s = w = make_float2(0.0f, 0.0f);
    }
    ((float2*)(out + S     ))[i] = c;
    ((float2*)(out + 3 * S ))[i] = s;
    ((float2*)(out + 5 * S ))[i] = w;
}

// Grid-stride, 4-wide ILP batched, ALL 32-bit indexing (total4 < 2^31):
// front-batched loads give MLP>=4; int indices keep regs <= 32 for full occ.
__global__ void __launch_bounds__(CLS_THREADS) merge_class_kernel(
    const float*  __restrict__ obj,
    const float4* __restrict__ cls,
    float4* __restrict__ out_t,
    float4* __restrict__ out_m,
    int total4)   // = S * C4  (14.55M, fits int)
{
    const int chunk  = CLS_THREADS * UNROLL;
    const int stride = gridDim.x * chunk;
    int base = blockIdx.x * chunk + threadIdx.x;

    for (; base < total4; base += stride) {
        int  idx[UNROLL];
        bool ok[UNROLL];
        bool mk[UNROLL];
#pragma unroll
        for (int j = 0; j < UNROLL; j++) {
            idx[j] = base + j * CLS_THREADS;
            ok[j]  = idx[j] < total4;
            mk[j]  = ok[j] && (obj[(unsigned)idx[j] / C4] > 0.0f);
        }
        float4 c[UNROLL];
#pragma unroll
        for (int j = 0; j < UNROLL; j++)
            c[j] = mk[j] ? __ldcs(&cls[idx[j]])
                         : make_float4(-1.0f, -1.0f, -1.0f, -1.0f);
#pragma unroll
        for (int j = 0; j < UNROLL; j++) {
            if (!ok[j]) continue;
            float4 mv;
            if (mk[j]) {
                mv.x = (c[j].x >= 0.0f) ? 1.0f : 0.0f;
                mv.y = (c[j].y >= 0.0f) ? 1.0f : 0.0f;
                mv.z = (c[j].z >= 0.0f) ? 1.0f : 0.0f;
                mv.w = (c[j].w >= 0.0f) ? 1.0f : 0.0f;
            } else {
                mv = make_float4(0.0f, 0.0f, 0.0f, 0.0f);
            }
            __stcs(&out_t[idx[j]], c[j]);
            __stcs(&out_m[idx[j]], mv);
        }
    }
}

extern "C" void kernel_launch(void* const* d_in, const int* in_sizes, int n_in,
                              void* d_out, int out_size)
{
    const float4* bp  = (const float4*)d_in[0];
    const float4* gt  = (const float4*)d_in[1];
    const float*  obj = (const float*) d_in[2];
    const float2* cen = (const float2*)d_in[3];
    const float2* sca = (const float2*)d_in[4];
    const float2* wei = (const float2*)d_in[5];
    const float*  cls = (const float*) d_in[6];

    const long long S = in_sizes[2];      // b * N
    const int N = (int)(S / BATCH);
    float* out = (float*)d_out;

    {
        dim3 block(256, 1, 1);
        dim3 grid((N + 255) / 256, BATCH, 1);
        merge_main_kernel<<<grid, block>>>(bp, gt, obj, cen, sca, wei, out, N, S);
    }
    {
        const int total4 = (int)(S * C4);
        float4* out_t = (float4*)(out + 7LL  * S);
        float4* out_m = (float4*)(out + 87LL * S);
        merge_class_kernel<<<CLS_BLOCKS, CLS_THREADS>>>(obj, (const float4*)cls,
                                                        out_t, out_m, total4);
    }
}

// round 10
// speedup vs baseline: 1.1020x; 1.1020x over previous
#include <cuda_runtime.h>

// YOLOV3TargetMerger: b=32, N=22743, M=50, C=80
// Inputs: 0 box_preds[b,N,4] 1 gt_boxes[b,M,4] 2 obj_t[b,N,1]
//         3 centers_t[b,N,2] 4 scales_t[b,N,2] 5 weights_t[b,N,2] 6 clas_t[b,N,80]
// Output (concat f32): obj[S], cen[2S], sca[2S], wei[2S], cls_t[80S], cls_m[80S]
//
// Two independent kernels (disjoint I/O) run CONCURRENTLY via stream fork/join
// inside graph capture: class stream (~100us, bandwidth-bound long pole) on the
// capture stream, main (~7us) on a second stream underneath it.

#define BATCH 32
#define MGT   50
#define NCLS  80
#define C4    (NCLS / 4)
#define THR   0.7f
#define EPSF  1e-12f

__global__ void __launch_bounds__(256) merge_main_kernel(
    const float4* __restrict__ bp,
    const float4* __restrict__ gt,
    const float*  __restrict__ obj,
    const float2* __restrict__ cen,
    const float2* __restrict__ sca,
    const float2* __restrict__ wei,
    float* __restrict__ out,
    int N, long long S)
{
    __shared__ float4 sgt[MGT];
    __shared__ float  sarea[MGT];
    __shared__ int    scnt;

    const int b = blockIdx.y;
    const int t = threadIdx.x;

    // compact gt boxes: non-positive width/height => inter==0 vs every anchor,
    // which can never produce a hit (needs d>0, then 0 > 0.7*d is false).
    if (t == 0) scnt = 0;
    __syncthreads();
    if (t < MGT) {
        const float4 g = gt[b * MGT + t];
        if (g.z > g.x && g.w > g.y) {
            const int k = atomicAdd(&scnt, 1);
            sgt[k]   = g;
            sarea[k] = (g.z - g.x) * (g.w - g.y);
        }
    }
    __syncthreads();
    const int K = scnt;                       // ~12.5 expected

    const int n = blockIdx.x * blockDim.x + t;
    if (n >= N) return;
    const long long i = (long long)b * N + n;

    const float o    = obj[i];
    const bool  mask = (o > 0.0f);

    float objout;
    if (mask) {
        objout = o;                           // IOU result unused -> skip loop
    } else {
        const float4 p = bp[i];
        const float area_p = (p.z - p.x) * (p.w - p.y);

        bool hit = false, ambig = false;
        for (int m = 0; m < K; m++) {
            const float4 g = sgt[m];
            const float w = fmaxf(fminf(p.z, g.z) - fmaxf(p.x, g.x), 0.0f);
            const float h = fmaxf(fminf(p.w, g.w) - fmaxf(p.y, g.y), 0.0f);
            const float inter = w * h;
            float u = area_p + sarea[m];
            u = u - inter;
            const float d = u + EPSF;         // ref denominator, same op order
            const float thr  = THR * d;
            const float diff = inter - thr;
            const float marg = 1e-6f * thr;
            const bool pos = (d > 0.0f);
            hit   = hit   | (pos & (diff >  marg));
            ambig = ambig | (pos & (fabsf(diff) <= marg));
        }
        if (ambig) {                          // rare: redo exactly (IEEE div)
            hit = false;
            for (int m = 0; m < K; m++) {
                const float4 g = sgt[m];
                const float w = fmaxf(fminf(p.z, g.z) - fmaxf(p.x, g.x), 0.0f);
                const float h = fmaxf(fminf(p.w, g.w) - fmaxf(p.y, g.y), 0.0f);
                const float inter = w * h;
                float u = area_p + sarea[m];
                u = u - inter;
                const float d = u + EPSF;
                hit = hit | ((inter / d) > THR);  // d<0 -> iou<=0 -> false (== ref)
            }
        }
        objout = hit ? -1.0f : 0.0f;
    }

    out[i] = objout;

    float2 c, s, w;
    if (mask) {
        c = cen[i]; s = sca[i]; w = wei[i];   // only read when used
    } else {
        c = s = w = make_float2(0.0f, 0.0f);
    }
    ((float2*)(out + S     ))[i] = c;
    ((float2*)(out + 3 * S ))[i] = s;
    ((float2*)(out + 5 * S ))[i] = w;
}

__global__ void __launch_bounds__(256) merge_class_kernel(
    const float*  __restrict__ obj,
    const float4* __restrict__ cls,
    float4* __restrict__ out_t,
    float4* __restrict__ out_m,
    int total4)   // = S * C4  (14.55M, fits int)
{
    const int idx = blockIdx.x * blockDim.x + threadIdx.x;
    if (idx >= total4) return;

    const int anchor = (int)((unsigned)idx / C4);
    const bool mask = (obj[anchor] > 0.0f);   // uniform over each anchor's 20 lanes

    float4 t, m;
    if (mask) {
        const float4 c = __ldcs(&cls[idx]);   // only ~50% of anchors read cls
        t = c;
        m.x = (c.x >= 0.0f) ? 1.0f : 0.0f;
        m.y = (c.y >= 0.0f) ? 1.0f : 0.0f;
        m.z = (c.z >= 0.0f) ? 1.0f : 0.0f;
        m.w = (c.w >= 0.0f) ? 1.0f : 0.0f;
    } else {
        t = make_float4(-1.0f, -1.0f, -1.0f, -1.0f);
        m = make_float4(0.0f, 0.0f, 0.0f, 0.0f);
    }

    __stcs(&out_t[idx], t);
    __stcs(&out_m[idx], m);
}

static cudaStream_t g_s2 = 0;
static cudaEvent_t  g_fork = 0, g_join = 0;

extern "C" void kernel_launch(void* const* d_in, const int* in_sizes, int n_in,
                              void* d_out, int out_size)
{
    const float4* bp  = (const float4*)d_in[0];
    const float4* gt  = (const float4*)d_in[1];
    const float*  obj = (const float*) d_in[2];
    const float2* cen = (const float2*)d_in[3];
    const float2* sca = (const float2*)d_in[4];
    const float2* wei = (const float2*)d_in[5];
    const float*  cls = (const float*) d_in[6];

    const long long S = in_sizes[2];      // b * N
    const int N = (int)(S / BATCH);
    float* out = (float*)d_out;

    // One-time resource init (happens on the uncaptured correctness call;
    // no device memory is allocated — streams/events only).
    if (g_s2 == 0) {
        cudaStreamCreateWithFlags(&g_s2, cudaStreamNonBlocking);
        cudaEventCreateWithFlags(&g_fork, cudaEventDisableTiming);
        cudaEventCreateWithFlags(&g_join, cudaEventDisableTiming);
    }

    // Fork: main kernel runs concurrently on g_s2 under the class stream.
    cudaEventRecord(g_fork, 0);
    cudaStreamWaitEvent(g_s2, g_fork, 0);

    {   // main path (small) — side stream
        dim3 block(256, 1, 1);
        dim3 grid((N + 255) / 256, BATCH, 1);
        merge_main_kernel<<<grid, block, 0, g_s2>>>(bp, gt, obj, cen, sca, wei,
                                                    out, N, S);
    }
    {   // class path (long pole) — capture/default stream
        const int total4 = (int)(S * C4);
        float4* out_t = (float4*)(out + 7LL  * S);
        float4* out_m = (float4*)(out + 87LL * S);
        const int blocks = (total4 + 255) / 256;
        merge_class_kernel<<<blocks, 256>>>(obj, (const float4*)cls,
                                            out_t, out_m, total4);
    }

    // Join: default stream waits for the side stream's kernel.
    cudaEventRecord(g_join, g_s2);
    cudaStreamWaitEvent(0, g_join, 0);
}